// round 1
// baseline (speedup 1.0000x reference)
#include <cuda_runtime.h>

#define NMAX  100000
#define F_IN  256
#define HID   128
#define H2    64

// -------- device scratch (no allocations allowed) --------
__device__ float g_W1[F_IN * 2 * HID];          // [256][256], cols interleaved: 2j=z_j, 2j+1=h_j
__device__ float g_W2[HID * 2 * H2];            // [128][128], interleaved
__device__ float g_h1[(size_t)NMAX * HID];      // layer-1 output

typedef unsigned long long u64;

__device__ __forceinline__ u64 pack2(float x) {
    u64 r;
    asm("mov.b64 %0, {%1, %2};" : "=l"(r) : "f"(x), "f"(x));
    return r;
}
__device__ __forceinline__ void fma2(u64& d, u64 a, u64 b) {
    asm("fma.rn.f32x2 %0, %1, %2, %0;" : "+l"(d) : "l"(a), "l"(b));
}
__device__ __forceinline__ void unpack2(u64 v, float& lo, float& hi) {
    asm("mov.b64 {%0, %1}, %2;" : "=f"(lo), "=f"(hi) : "l"(v));
}

// h = relu( sigmoid(-uz) * tanh(uh) )   [= relu((1-z)*h_tilde) since h0=0]
__device__ __forceinline__ float gate_act(float uz, float uh) {
    float s = 1.0f / (1.0f + __expf(uz));   // sigmoid(-uz) = 1-z
    float t = tanhf(uh);
    return fmaxf(s * t, 0.0f);
}

// ---------------- weight prep: combine W[0,0]+W[1,0], interleave z/h cols ----------------
__global__ void prep_kernel(const float* __restrict__ wz1, const float* __restrict__ wh1,
                            const float* __restrict__ wz2, const float* __restrict__ wh2) {
    int i = blockIdx.x * blockDim.x + threadIdx.x;
    // W1: (2,1,384,128) -> use rows k<256. element (e,0,k,j) at e*384*128 + k*128 + j
    if (i < 256 * 128) {
        int k = i >> 7, j = i & 127;
        g_W1[k * 256 + 2 * j]     = wz1[k * 128 + j] + wz1[384 * 128 + k * 128 + j];
        g_W1[k * 256 + 2 * j + 1] = wh1[k * 128 + j] + wh1[384 * 128 + k * 128 + j];
    }
    // W2: (2,1,192,64) -> rows k<128. element (e,0,k,j) at e*192*64 + k*64 + j
    if (i < 128 * 64) {
        int k = i >> 6, j = i & 63;
        g_W2[k * 128 + 2 * j]     = wz2[k * 64 + j] + wz2[192 * 64 + k * 64 + j];
        g_W2[k * 128 + 2 * j + 1] = wh2[k * 64 + j] + wh2[192 * 64 + k * 64 + j];
    }
}

// ---------------- layer 1: h1 = act(x @ W1i + b), BM=64 BN=256 BK=16 ----------------
__global__ __launch_bounds__(256, 2)
void layer1_kernel(const float* __restrict__ x,
                   const float* __restrict__ bz, const float* __restrict__ bh, int n) {
    __shared__ __align__(16) float Xs[64 * 16];
    __shared__ __align__(16) float Ws[16 * 256];

    const int tid = threadIdx.x;
    const int ty = tid >> 4, tx = tid & 15;
    const int r0 = blockIdx.x * 64;

    u64 acc[4][8];
#pragma unroll
    for (int i = 0; i < 4; i++)
#pragma unroll
        for (int c = 0; c < 8; c++) acc[i][c] = 0ull;

    for (int kt = 0; kt < 16; kt++) {
        const int k0 = kt * 16;
#pragma unroll
        for (int l = tid; l < 64 * 16; l += 256) {
            int row = l >> 4, kk = l & 15;
            int gr = r0 + row;
            Xs[l] = (gr < n) ? x[gr * F_IN + k0 + kk] : 0.0f;
        }
#pragma unroll
        for (int l = tid; l < 16 * 256; l += 256)
            Ws[l] = g_W1[k0 * 256 + l];
        __syncthreads();

        const u64* Ws2 = (const u64*)Ws;   // [16][128] f32x2 col-pairs
#pragma unroll
        for (int kk = 0; kk < 16; kk++) {
            u64 a[4];
#pragma unroll
            for (int i = 0; i < 4; i++) a[i] = pack2(Xs[(ty * 4 + i) * 16 + kk]);
            u64 w[8];
#pragma unroll
            for (int c = 0; c < 8; c++) w[c] = Ws2[kk * 128 + tx + 16 * c];
#pragma unroll
            for (int i = 0; i < 4; i++)
#pragma unroll
                for (int c = 0; c < 8; c++) fma2(acc[i][c], a[i], w[c]);
        }
        __syncthreads();
    }

#pragma unroll
    for (int i = 0; i < 4; i++) {
        int gr = r0 + ty * 4 + i;
        if (gr >= n) continue;
#pragma unroll
        for (int c = 0; c < 8; c++) {
            int j = tx + 16 * c;               // h1 column
            float uz, uh;
            unpack2(acc[i][c], uz, uh);
            uz += bz[j]; uh += bh[j];
            g_h1[gr * HID + j] = gate_act(uz, uh);
        }
    }
}

// ------- layer 2 + lin1 + lin2 fused: BM=64 BN=128 BK=16, h2 stays in SMEM -------
__global__ __launch_bounds__(256, 2)
void layer2_kernel(const float* __restrict__ bz, const float* __restrict__ bh,
                   const float* __restrict__ w3, const float* __restrict__ b3,
                   const float* __restrict__ w4, const float* __restrict__ b4,
                   float* __restrict__ out, int n) {
    __shared__ __align__(16) float Xs[64 * 16];
    __shared__ __align__(16) float Ws[16 * 128];
    __shared__ float h2s[64 * 65];             // pad 1 -> conflict-free row reads
    __shared__ float w3s[64 * 16];
    __shared__ float b3s[16], w4s[16];
    __shared__ float red[4 * 64];

    const int tid = threadIdx.x;
    const int ty = tid >> 4, tx = tid & 15;
    const int r0 = blockIdx.x * 64;

    for (int l = tid; l < 64 * 16; l += 256) w3s[l] = w3[l];
    if (tid < 16) { b3s[tid] = b3[tid]; w4s[tid] = w4[tid]; }

    u64 acc[4][4];
#pragma unroll
    for (int i = 0; i < 4; i++)
#pragma unroll
        for (int c = 0; c < 4; c++) acc[i][c] = 0ull;

    for (int kt = 0; kt < 8; kt++) {
        const int k0 = kt * 16;
#pragma unroll
        for (int l = tid; l < 64 * 16; l += 256) {
            int row = l >> 4, kk = l & 15;
            int gr = r0 + row;
            Xs[l] = (gr < n) ? g_h1[gr * HID + k0 + kk] : 0.0f;
        }
#pragma unroll
        for (int l = tid; l < 16 * 128; l += 256)
            Ws[l] = g_W2[k0 * 128 + l];
        __syncthreads();

        const u64* Ws2 = (const u64*)Ws;   // [16][64] f32x2 col-pairs
#pragma unroll
        for (int kk = 0; kk < 16; kk++) {
            u64 a[4];
#pragma unroll
            for (int i = 0; i < 4; i++) a[i] = pack2(Xs[(ty * 4 + i) * 16 + kk]);
            u64 w[4];
#pragma unroll
            for (int c = 0; c < 4; c++) w[c] = Ws2[kk * 64 + tx + 16 * c];
#pragma unroll
            for (int i = 0; i < 4; i++)
#pragma unroll
                for (int c = 0; c < 4; c++) fma2(acc[i][c], a[i], w[c]);
        }
        __syncthreads();
    }

    // h2 -> SMEM (zero-padded rows produce finite garbage; stores guarded later)
#pragma unroll
    for (int i = 0; i < 4; i++) {
        int lr = ty * 4 + i;
#pragma unroll
        for (int c = 0; c < 4; c++) {
            int j = tx + 16 * c;               // h2 column (0..63)
            float uz, uh;
            unpack2(acc[i][c], uz, uh);
            uz += bz[j]; uh += bh[j];
            h2s[lr * 65 + j] = gate_act(uz, uh);
        }
    }
    __syncthreads();

    // lin1(relu) + lin2: 4 threads per row, each handles 4 of 16 hidden units
    {
        const int lrow = tid & 63;
        const int q = tid >> 6;                // 0..3
        float s[4];
#pragma unroll
        for (int u = 0; u < 4; u++) s[u] = b3s[q * 4 + u];
#pragma unroll 4
        for (int j = 0; j < 64; j++) {
            float v = h2s[lrow * 65 + j];
#pragma unroll
            for (int u = 0; u < 4; u++) s[u] = fmaf(v, w3s[j * 16 + q * 4 + u], s[u]);
        }
        float partial = 0.0f;
#pragma unroll
        for (int u = 0; u < 4; u++) partial += fmaxf(s[u], 0.0f) * w4s[q * 4 + u];
        red[q * 64 + lrow] = partial;
    }
    __syncthreads();
    if (tid < 64) {
        int gr = r0 + tid;
        if (gr < n)
            out[gr] = b4[0] + red[tid] + red[64 + tid] + red[128 + tid] + red[192 + tid];
    }
}

extern "C" void kernel_launch(void* const* d_in, const int* in_sizes, int n_in,
                              void* d_out, int out_size) {
    const float* x   = (const float*)d_in[0];
    // d_in[1] edge_index, d_in[2] edge_weight: unused (K=1 DConv has no propagation)
    const float* wz1 = (const float*)d_in[3];
    const float* bz1 = (const float*)d_in[4];
    // d_in[5..6]: w_r1/b_r1 unused (r gated by h0=0)
    const float* wh1 = (const float*)d_in[7];
    const float* bh1 = (const float*)d_in[8];
    const float* wz2 = (const float*)d_in[9];
    const float* bz2 = (const float*)d_in[10];
    // d_in[11..12]: w_r2/b_r2 unused
    const float* wh2 = (const float*)d_in[13];
    const float* bh2 = (const float*)d_in[14];
    const float* w3  = (const float*)d_in[15];
    const float* b3  = (const float*)d_in[16];
    const float* w4  = (const float*)d_in[17];
    const float* b4  = (const float*)d_in[18];

    const int n = in_sizes[0] / F_IN;          // 100000
    const int nb = (n + 63) / 64;

    prep_kernel<<<128, 256>>>(wz1, wh1, wz2, wh2);
    layer1_kernel<<<nb, 256>>>(x, bz1, bh1, n);
    layer2_kernel<<<nb, 256>>>(bz2, bh2, w3, b3, w4, b4, (float*)d_out, n);
}

// round 6
// speedup vs baseline: 1.8696x; 1.8696x over previous
#include <cuda_runtime.h>
#include <cuda_bf16.h>
#include <cstdint>

#define NB_MAX 782            // ceil(100000/128)

// ---------------- device scratch (no allocs allowed) ----------------
// W1 pre-swizzled images: [kt=4][hi 32KB | lo 32KB]  (B operand [N=256][K=64] per chunk)
__device__ __align__(16) unsigned char g_W1sw[4 * 65536];
// W2 pre-swizzled: [kt=2][hi 16KB | lo 16KB]  ([N=128][K=64] per chunk)
__device__ __align__(16) unsigned char g_W2sw[2 * 32768];
// h1 per-tile A images: [ck=2][hi 16KB | lo 16KB] = 64KB per 128-row tile
__device__ __align__(16) unsigned char g_h1img[(size_t)NB_MAX * 65536];

// ---------------- helpers ----------------
__device__ __forceinline__ uint32_t s2u(const void* p) {
    uint32_t a;
    asm("{ .reg .u64 t; cvta.to.shared.u64 t, %1; cvt.u32.u64 %0, t; }" : "=r"(a) : "l"(p));
    return a;
}
#define SW128(o) ((o) ^ (((o) >> 3) & 0x70))

#define LDSM4(R0, R1, R2, R3, A) \
    asm volatile("ldmatrix.sync.aligned.m8n8.x4.shared.b16 {%0,%1,%2,%3}, [%4];" \
                 : "=r"(R0), "=r"(R1), "=r"(R2), "=r"(R3) : "r"(A))

__device__ __forceinline__ void mma_bf16(float d[4], const uint32_t a[4], const uint32_t b[2]) {
    asm volatile(
        "mma.sync.aligned.m16n8k16.row.col.f32.bf16.bf16.f32 "
        "{%0,%1,%2,%3}, {%4,%5,%6,%7}, {%8,%9}, {%0,%1,%2,%3};"
        : "+f"(d[0]), "+f"(d[1]), "+f"(d[2]), "+f"(d[3])
        : "r"(a[0]), "r"(a[1]), "r"(a[2]), "r"(a[3]), "r"(b[0]), "r"(b[1]));
}

__device__ __forceinline__ void cpa16(uint32_t saddr, const void* g) {
    asm volatile("cp.async.cg.shared.global [%0], [%1], 16;" :: "r"(saddr), "l"(g));
}
#define CP_COMMIT() asm volatile("cp.async.commit_group;" ::: "memory")
#define CP_WAIT0()  asm volatile("cp.async.wait_group 0;" ::: "memory")

// h = relu( sigmoid(-uz) * tanh(uh) )   [GRU cell with h0 = 0]
__device__ __forceinline__ float gate_act(float uz, float uh) {
    float s = 1.0f / (1.0f + __expf(uz));
    float t = tanhf(uh);
    return fmaxf(s * t, 0.0f);
}

// ---------------- prep: combine W[0,0]+W[1,0], interleave z/h cols, split bf16, swizzle ----------------
__global__ void prep_kernel(const float* __restrict__ wz1, const float* __restrict__ wh1,
                            const float* __restrict__ wz2, const float* __restrict__ wh2) {
    int i = blockIdx.x * blockDim.x + threadIdx.x;   // 65536 threads
    {   // W1: B operand [n=256][k=256]; n=2j -> z_j, n=2j+1 -> h_j
        int nn = i >> 8, k = i & 255;
        int j = nn >> 1;
        const float* src = (nn & 1) ? wh1 : wz1;
        float w = src[k * 128 + j] + src[49152 + k * 128 + j];
        __nv_bfloat16 hb = __float2bfloat16(w);
        __nv_bfloat16 lb = __float2bfloat16(w - __bfloat162float(hb));
        int kt = k >> 6, kk = k & 63;
        uint32_t o = (uint32_t)(kt * 65536) + SW128((uint32_t)(nn * 128 + kk * 2));
        *(__nv_bfloat16*)(g_W1sw + o) = hb;
        *(__nv_bfloat16*)(g_W1sw + o + 32768) = lb;
    }
    if (i < 16384) {   // W2: [n=128][k=128]
        int nn = i >> 7, k = i & 127;
        int j = nn >> 1;
        const float* src = (nn & 1) ? wh2 : wz2;
        float w = src[k * 64 + j] + src[12288 + k * 64 + j];
        __nv_bfloat16 hb = __float2bfloat16(w);
        __nv_bfloat16 lb = __float2bfloat16(w - __bfloat162float(hb));
        int kt = k >> 6, kk = k & 63;
        uint32_t o = (uint32_t)(kt * 32768) + SW128((uint32_t)(nn * 128 + kk * 2));
        *(__nv_bfloat16*)(g_W2sw + o) = hb;
        *(__nv_bfloat16*)(g_W2sw + o + 16384) = lb;
    }
}

// =================== layer 1: BM=128, BN=256, K=256 (4 chunks of 64) ===================
// smem: [A_hi 16K][A_lo 16K][B 64K = Bh 32K | Bl 32K][bzs 512][bhs 512]   total 99328
// Stage (h1 image) reuses the B region after the last chunk.
__global__ void __launch_bounds__(512, 1)
layer1_mma(const float* __restrict__ x, const float* __restrict__ bz,
           const float* __restrict__ bh, int n) {
    extern __shared__ __align__(128) char sm[];
    const uint32_t sb = s2u(sm);
    const int tid = threadIdx.x, l = tid & 31, w = tid >> 5;
    const int wm = w >> 2, wn = w & 3;          // 4x4 warp grid
    float* bzs = (float*)(sm + 98304);
    float* bhs = (float*)(sm + 98816);
    if (tid < 128) { bzs[tid] = bz[tid]; bhs[tid] = bh[tid]; }

    float acc[2][8][4];
#pragma unroll
    for (int mi = 0; mi < 2; mi++)
#pragma unroll
        for (int nj = 0; nj < 8; nj++)
#pragma unroll
            for (int q = 0; q < 4; q++) acc[mi][nj][q] = 0.0f;

    // lane geometry for ldmatrix
    const int arow0 = wm * 32 + (l & 15);                 // + mi*16
    const uint32_t kba = (uint32_t)(((l >> 4) & 1) * 16);
    const int brow0 = wn * 64 + 8 * ((l >> 4) & 1) + (l & 7);   // + g*16
    const uint32_t kbb = (uint32_t)(((l >> 3) & 1) * 16);

    const int r0 = blockIdx.x * 128;
    const int iq = tid & 15;

    for (int kt = 0; kt < 4; kt++) {
        // --- B chunk via cp.async (overlaps with A convert) ---
        {
            const char* gB = (const char*)g_W1sw + (size_t)kt * 65536;
#pragma unroll
            for (int i = 0; i < 8; i++) {
                int idx = tid + i * 512;
                cpa16(sb + 32768u + (uint32_t)idx * 16u, gB + (size_t)idx * 16);
            }
            CP_COMMIT();
        }
        // --- A chunk: fp32 -> bf16 hi/lo, swizzled STS ---
#pragma unroll
        for (int pass = 0; pass < 4; pass++) {
            int row = (tid >> 4) + pass * 32;
            int gr = r0 + row; if (gr >= n) gr = n - 1;
            float4 v = *(const float4*)(x + (size_t)gr * 256 + kt * 64 + iq * 4);
            __nv_bfloat16 h0 = __float2bfloat16(v.x), h1 = __float2bfloat16(v.y);
            __nv_bfloat16 h2 = __float2bfloat16(v.z), h3 = __float2bfloat16(v.w);
            __nv_bfloat16 l0 = __float2bfloat16(v.x - __bfloat162float(h0));
            __nv_bfloat16 l1 = __float2bfloat16(v.y - __bfloat162float(h1));
            __nv_bfloat16 l2 = __float2bfloat16(v.z - __bfloat162float(h2));
            __nv_bfloat16 l3 = __float2bfloat16(v.w - __bfloat162float(h3));
            uint32_t o = SW128((uint32_t)(row * 128 + iq * 8));
            uint2 hp = make_uint2((uint32_t)__bfloat16_as_ushort(h0) | ((uint32_t)__bfloat16_as_ushort(h1) << 16),
                                  (uint32_t)__bfloat16_as_ushort(h2) | ((uint32_t)__bfloat16_as_ushort(h3) << 16));
            uint2 lp = make_uint2((uint32_t)__bfloat16_as_ushort(l0) | ((uint32_t)__bfloat16_as_ushort(l1) << 16),
                                  (uint32_t)__bfloat16_as_ushort(l2) | ((uint32_t)__bfloat16_as_ushort(l3) << 16));
            *(uint2*)(sm + o) = hp;
            *(uint2*)(sm + 16384 + o) = lp;
        }
        CP_WAIT0();
        __syncthreads();

        // --- compute: 3-term split (Ah·Bh, Al·Bh, Ah·Bl) ---
#pragma unroll
        for (int kk = 0; kk < 4; kk++) {
            uint32_t ah[2][4], al[2][4], bfr[8][2];
#pragma unroll
            for (int mi = 0; mi < 2; mi++) {
                int row = arow0 + mi * 16;
                uint32_t off = (uint32_t)(row * 128) + (((uint32_t)(kk * 32) + kba) ^ (uint32_t)((row & 7) << 4));
                LDSM4(ah[mi][0], ah[mi][1], ah[mi][2], ah[mi][3], sb + off);
            }
#pragma unroll
            for (int g = 0; g < 4; g++) {
                int row = brow0 + g * 16;
                uint32_t off = (uint32_t)(row * 128) + (((uint32_t)(kk * 32) + kbb) ^ (uint32_t)((row & 7) << 4));
                LDSM4(bfr[2 * g][0], bfr[2 * g][1], bfr[2 * g + 1][0], bfr[2 * g + 1][1], sb + 32768u + off);
            }
#pragma unroll
            for (int mi = 0; mi < 2; mi++)
#pragma unroll
                for (int nj = 0; nj < 8; nj++) mma_bf16(acc[mi][nj], ah[mi], bfr[nj]);
#pragma unroll
            for (int mi = 0; mi < 2; mi++) {
                int row = arow0 + mi * 16;
                uint32_t off = (uint32_t)(row * 128) + (((uint32_t)(kk * 32) + kba) ^ (uint32_t)((row & 7) << 4));
                LDSM4(al[mi][0], al[mi][1], al[mi][2], al[mi][3], sb + 16384u + off);
            }
#pragma unroll
            for (int mi = 0; mi < 2; mi++)
#pragma unroll
                for (int nj = 0; nj < 8; nj++) mma_bf16(acc[mi][nj], al[mi], bfr[nj]);
#pragma unroll
            for (int g = 0; g < 4; g++) {
                int row = brow0 + g * 16;
                uint32_t off = (uint32_t)(row * 128) + (((uint32_t)(kk * 32) + kbb) ^ (uint32_t)((row & 7) << 4));
                LDSM4(bfr[2 * g][0], bfr[2 * g][1], bfr[2 * g + 1][0], bfr[2 * g + 1][1], sb + 65536u + off);
            }
#pragma unroll
            for (int mi = 0; mi < 2; mi++)
#pragma unroll
                for (int nj = 0; nj < 8; nj++) mma_bf16(acc[mi][nj], ah[mi], bfr[nj]);
        }
        __syncthreads();
    }

    // --- epilogue: act, bf16 split, stage as layer-2 A image (in B region) ---
#pragma unroll
    for (int mi = 0; mi < 2; mi++)
#pragma unroll
        for (int nj = 0; nj < 8; nj++) {
            int rlo = wm * 32 + mi * 16 + (l >> 2);
            int j = wn * 32 + nj * 4 + (l & 3);
            float v0 = gate_act(acc[mi][nj][0] + bzs[j], acc[mi][nj][1] + bhs[j]);
            float v1 = gate_act(acc[mi][nj][2] + bzs[j], acc[mi][nj][3] + bhs[j]);
            int ck = j >> 6, kk2 = j & 63;
            uint32_t base = 32768u + (uint32_t)(ck * 32768);
            {
                __nv_bfloat16 hb = __float2bfloat16(v0);
                __nv_bfloat16 lb = __float2bfloat16(v0 - __bfloat162float(hb));
                uint32_t o = base + SW128((uint32_t)(rlo * 128 + kk2 * 2));
                *(__nv_bfloat16*)(sm + o) = hb;
                *(__nv_bfloat16*)(sm + o + 16384) = lb;
            }
            {
                __nv_bfloat16 hb = __float2bfloat16(v1);
                __nv_bfloat16 lb = __float2bfloat16(v1 - __bfloat162float(hb));
                uint32_t o = base + SW128((uint32_t)((rlo + 8) * 128 + kk2 * 2));
                *(__nv_bfloat16*)(sm + o) = hb;
                *(__nv_bfloat16*)(sm + o + 16384) = lb;
            }
        }
    __syncthreads();
    {   // stage (64KB) -> g_h1img tile, coalesced
        const uint4* s4 = (const uint4*)(sm + 32768);
        uint4* d4 = (uint4*)(g_h1img + (size_t)blockIdx.x * 65536);
#pragma unroll
        for (int i = 0; i < 8; i++) d4[tid + i * 512] = s4[tid + i * 512];
    }
}

// =================== layer 2 + lin1 + lin2: BM=128, BN=128, K=128 (2 chunks) ===================
// smem: [A_hi 16K][A_lo 16K][B_hi 16K][B_lo 16K][w3s 4K][b3s][w4s][bzs][bhs]  total 70272
// h2s (128*65*4 = 33280B) overlaps A/B regions after the mainloop.
__global__ void __launch_bounds__(256, 1)
layer2_mma(const float* __restrict__ bz, const float* __restrict__ bh,
           const float* __restrict__ w3, const float* __restrict__ b3,
           const float* __restrict__ w4, const float* __restrict__ b4,
           float* __restrict__ out, int n) {
    extern __shared__ __align__(128) char sm[];
    const uint32_t sb = s2u(sm);
    const int tid = threadIdx.x, l = tid & 31, w = tid >> 5;
    const int wm = w >> 1, wn = w & 1;          // 4x2 warp grid
    float* w3s = (float*)(sm + 65536);
    float* b3s = (float*)(sm + 69632);
    float* w4s = (float*)(sm + 69696);
    float* bzs = (float*)(sm + 69760);
    float* bhs = (float*)(sm + 70016);
#pragma unroll
    for (int i = 0; i < 4; i++) w3s[tid + i * 256] = w3[tid + i * 256];
    if (tid < 16) { b3s[tid] = b3[tid]; w4s[tid] = w4[tid]; }
    if (tid < 64) { bzs[tid] = bz[tid]; bhs[tid] = bh[tid]; }

    float acc[2][8][4];
#pragma unroll
    for (int mi = 0; mi < 2; mi++)
#pragma unroll
        for (int nj = 0; nj < 8; nj++)
#pragma unroll
            for (int q = 0; q < 4; q++) acc[mi][nj][q] = 0.0f;

    const int arow0 = wm * 32 + (l & 15);
    const uint32_t kba = (uint32_t)(((l >> 4) & 1) * 16);
    const int brow0 = wn * 64 + 8 * ((l >> 4) & 1) + (l & 7);
    const uint32_t kbb = (uint32_t)(((l >> 3) & 1) * 16);

    const int r0 = blockIdx.x * 128;

    for (int kt = 0; kt < 2; kt++) {
        {   // A chunk (32KB) + B chunk (32KB) via cp.async
            const char* gA = (const char*)g_h1img + (size_t)blockIdx.x * 65536 + (size_t)kt * 32768;
            const char* gB = (const char*)g_W2sw + (size_t)kt * 32768;
#pragma unroll
            for (int i = 0; i < 8; i++) {
                int idx = tid + i * 256;
                cpa16(sb + (uint32_t)idx * 16u, gA + (size_t)idx * 16);
                cpa16(sb + 32768u + (uint32_t)idx * 16u, gB + (size_t)idx * 16);
            }
            CP_COMMIT();
        }
        CP_WAIT0();
        __syncthreads();

#pragma unroll
        for (int kk = 0; kk < 4; kk++) {
            uint32_t ah[2][4], al[2][4], bfr[8][2];
#pragma unroll
            for (int mi = 0; mi < 2; mi++) {
                int row = arow0 + mi * 16;
                uint32_t off = (uint32_t)(row * 128) + (((uint32_t)(kk * 32) + kba) ^ (uint32_t)((row & 7) << 4));
                LDSM4(ah[mi][0], ah[mi][1], ah[mi][2], ah[mi][3], sb + off);
            }
#pragma unroll
            for (int g = 0; g < 4; g++) {
                int row = brow0 + g * 16;
                uint32_t off = (uint32_t)(row * 128) + (((uint32_t)(kk * 32) + kbb) ^ (uint32_t)((row & 7) << 4));
                LDSM4(bfr[2 * g][0], bfr[2 * g][1], bfr[2 * g + 1][0], bfr[2 * g + 1][1], sb + 32768u + off);
            }
#pragma unroll
            for (int mi = 0; mi < 2; mi++)
#pragma unroll
                for (int nj = 0; nj < 8; nj++) mma_bf16(acc[mi][nj], ah[mi], bfr[nj]);
#pragma unroll
            for (int mi = 0; mi < 2; mi++) {
                int row = arow0 + mi * 16;
                uint32_t off = (uint32_t)(row * 128) + (((uint32_t)(kk * 32) + kba) ^ (uint32_t)((row & 7) << 4));
                LDSM4(al[mi][0], al[mi][1], al[mi][2], al[mi][3], sb + 16384u + off);
            }
#pragma unroll
            for (int mi = 0; mi < 2; mi++)
#pragma unroll
                for (int nj = 0; nj < 8; nj++) mma_bf16(acc[mi][nj], al[mi], bfr[nj]);
#pragma unroll
            for (int g = 0; g < 4; g++) {
                int row = brow0 + g * 16;
                uint32_t off = (uint32_t)(row * 128) + (((uint32_t)(kk * 32) + kbb) ^ (uint32_t)((row & 7) << 4));
                LDSM4(bfr[2 * g][0], bfr[2 * g][1], bfr[2 * g + 1][0], bfr[2 * g + 1][1], sb + 49152u + off);
            }
#pragma unroll
            for (int mi = 0; mi < 2; mi++)
#pragma unroll
                for (int nj = 0; nj < 8; nj++) mma_bf16(acc[mi][nj], ah[mi], bfr[nj]);
        }
        __syncthreads();
    }

    // --- epilogue: h2 -> smem (overlapping dead A/B regions) ---
    float* h2s = (float*)sm;    // [128][65]
#pragma unroll
    for (int mi = 0; mi < 2; mi++)
#pragma unroll
        for (int nj = 0; nj < 8; nj++) {
            int rlo = wm * 32 + mi * 16 + (l >> 2);
            int j = wn * 32 + nj * 4 + (l & 3);
            float v0 = gate_act(acc[mi][nj][0] + bzs[j], acc[mi][nj][1] + bhs[j]);
            float v1 = gate_act(acc[mi][nj][2] + bzs[j], acc[mi][nj][3] + bhs[j]);
            h2s[rlo * 65 + j] = v0;
            h2s[(rlo + 8) * 65 + j] = v1;
        }
    __syncthreads();

    // --- lin1(relu) + lin2: one thread per row ---
    if (tid < 128) {
        float s[16];
#pragma unroll
        for (int u = 0; u < 16; u++) s[u] = b3s[u];
#pragma unroll 4
        for (int j = 0; j < 64; j++) {
            float v = h2s[tid * 65 + j];
#pragma unroll
            for (int u = 0; u < 16; u++) s[u] = fmaf(v, w3s[j * 16 + u], s[u]);
        }
        float o2 = __ldg(b4);
#pragma unroll
        for (int u = 0; u < 16; u++) o2 += fmaxf(s[u], 0.0f) * w4s[u];
        int gr = r0 + tid;
        if (gr < n) out[gr] = o2;
    }
}

extern "C" void kernel_launch(void* const* d_in, const int* in_sizes, int n_in,
                              void* d_out, int out_size) {
    const float* x   = (const float*)d_in[0];
    const float* wz1 = (const float*)d_in[3];
    const float* bz1 = (const float*)d_in[4];
    const float* wh1 = (const float*)d_in[7];
    const float* bh1 = (const float*)d_in[8];
    const float* wz2 = (const float*)d_in[9];
    const float* bz2 = (const float*)d_in[10];
    const float* wh2 = (const float*)d_in[13];
    const float* bh2 = (const float*)d_in[14];
    const float* w3  = (const float*)d_in[15];
    const float* b3  = (const float*)d_in[16];
    const float* w4  = (const float*)d_in[17];
    const float* b4  = (const float*)d_in[18];

    const int n  = in_sizes[0] / 256;          // 100000
    const int nb = (n + 127) / 128;            // 782

    cudaFuncSetAttribute(layer1_mma, cudaFuncAttributeMaxDynamicSharedMemorySize, 99328);
    cudaFuncSetAttribute(layer2_mma, cudaFuncAttributeMaxDynamicSharedMemorySize, 70272);

    prep_kernel<<<256, 256>>>(wz1, wh1, wz2, wh2);
    layer1_mma<<<nb, 512, 99328>>>(x, bz1, bh1, n);
    layer2_mma<<<nb, 256, 70272>>>(bz2, bh2, w3, b3, w4, b4, (float*)d_out, n);
}